// round 14
// baseline (speedup 1.0000x reference)
#include <cuda_runtime.h>
#include <cuda_fp16.h>
#include <cstdint>

// ---------------- Problem constants ----------------
#define BATCH 16
#define NQ    2048
#define NK    2048
#define DIM   128
#define DVAL  128

// ---------------- Tiling ----------------
#define BM 64
#define BN 64
#define NTHREADS 128   // 4 warps; warp w owns q-rows [w*16, w*16+16)

// ---------------- Precomputed fp16 K + V (both natural [b][key][d] layout) ----------------
__device__ __half gK[BATCH * NK * DIM];
__device__ __half gV[BATCH * NK * DVAL];

// ---------------- SMEM layout (bytes) ----------------
// Per stage (both tiles 64 keys x 128 d fp16, padded row = 272 B, conflict-free):
#define KROW 272
#define SK    0
#define SV    17408                  // 64*272
#define STAGE 34816                  // 2*17408
#define NSTAGE 3
// Q staging overlays stage-2 region (prologue only; tile 2 is issued after frags are built)
#define SQ    (2 * STAGE)
#define SM_TOTAL (NSTAGE * STAGE)    // 104448 -> 2 CTAs/SM (204 KB)

// ---------------- PTX helpers ----------------
__device__ __forceinline__ uint32_t smem_u32(const void* p) {
    uint32_t a;
    asm("{ .reg .u64 t; cvta.to.shared.u64 t, %1; cvt.u32.u64 %0, t; }" : "=r"(a) : "l"(p));
    return a;
}
__device__ __forceinline__ void ldsm4(uint32_t* r, uint32_t addr) {
    asm volatile("ldmatrix.sync.aligned.m8n8.x4.shared.b16 {%0,%1,%2,%3}, [%4];"
                 : "=r"(r[0]), "=r"(r[1]), "=r"(r[2]), "=r"(r[3]) : "r"(addr));
}
__device__ __forceinline__ void ldsm4t(uint32_t* r, uint32_t addr) {
    asm volatile("ldmatrix.sync.aligned.m8n8.x4.trans.shared.b16 {%0,%1,%2,%3}, [%4];"
                 : "=r"(r[0]), "=r"(r[1]), "=r"(r[2]), "=r"(r[3]) : "r"(addr));
}
__device__ __forceinline__ void mma16816(float* c, const uint32_t* a, uint32_t b0, uint32_t b1) {
    asm volatile("mma.sync.aligned.m16n8k16.row.col.f32.f16.f16.f32 "
                 "{%0,%1,%2,%3}, {%4,%5,%6,%7}, {%8,%9}, {%0,%1,%2,%3};"
                 : "+f"(c[0]), "+f"(c[1]), "+f"(c[2]), "+f"(c[3])
                 : "r"(a[0]), "r"(a[1]), "r"(a[2]), "r"(a[3]), "r"(b0), "r"(b1));
}
#define CPA16(dst, src) \
    asm volatile("cp.async.cg.shared.global [%0], [%1], 16;" :: "r"(dst), "l"(src))
#define CPA_COMMIT() asm volatile("cp.async.commit_group;" ::: "memory")
#define CPA_WAIT1()  asm volatile("cp.async.wait_group 1;" ::: "memory")

// fp32 pair -> packed fp16x2
__device__ __forceinline__ uint32_t pack2(float a, float b) {
    __half2 H = __floats2half2_rn(a, b);
    return *reinterpret_cast<uint32_t*>(&H);
}

// ---------------- Fused precompute: K and V -> fp16, same layout ----------------
__global__ void kvconv_kernel(const float* __restrict__ K, const float* __restrict__ V) {
    const int i = blockIdx.x * blockDim.x + threadIdx.x;   // over float4s
    float4 k = ((const float4*)K)[i];
    float4 v = ((const float4*)V)[i];
    ((uint2*)gK)[i] = make_uint2(pack2(k.x, k.y), pack2(k.z, k.w));
    ((uint2*)gV)[i] = make_uint2(pack2(v.x, v.y), pack2(v.z, v.w));
}

// ---------------- Tile prefetch (all 128 threads; 16 CPA16 each) ----------------
__device__ __forceinline__ void issue_tile(uint32_t base, int st, int tid, int n0,
                                           const __half* __restrict__ gk,
                                           const __half* __restrict__ gv) {
    const uint32_t sb = base + st * STAGE;
    #pragma unroll
    for (int i = 0; i < 8; ++i) {              // K: 64 keys x 256 B
        int c = tid + NTHREADS * i;
        int key = c >> 4, seg = c & 15;
        CPA16(sb + SK + key * KROW + seg * 16,
              gk + (size_t)(n0 + key) * DIM + seg * 8);
    }
    #pragma unroll
    for (int i = 0; i < 8; ++i) {              // V: 64 keys x 256 B (same pattern)
        int c = tid + NTHREADS * i;
        int key = c >> 4, seg = c & 15;
        CPA16(sb + SV + key * KROW + seg * 16,
              gv + (size_t)(n0 + key) * DVAL + seg * 8);
    }
}

// ---------------- Main attention kernel ----------------
__global__ __launch_bounds__(NTHREADS, 2)    // occ 2: champion regime (regs ~242)
void fa_mma_kernel(const float* __restrict__ Q, const int* __restrict__ VL,
                   float* __restrict__ O)
{
    extern __shared__ char smem[];
    const uint32_t base = smem_u32(smem);
    const int tid  = threadIdx.x;
    const int warp = tid >> 5;
    const int lane = tid & 31;
    const int b    = blockIdx.y;        // q-tile-fast grid (champion config)
    const int q0   = blockIdx.x * BM;
    const int vlen = VL[b];
    const int nt   = (vlen + BN - 1) / BN;

    const __half* gk = gK + (size_t)b * NK * DIM;
    const __half* gv = gV + (size_t)b * NK * DVAL;

    // ---- Prologue: tiles 0,1 -> stages 0,1 (async); Q (fp16) staged into stage-2 area ----
    issue_tile(base, 0, tid, 0, gk, gv);
    CPA_COMMIT();                              // group g0 = tile 0
    if (nt > 1) issue_tile(base, 1, tid, BN, gk, gv);
    CPA_COMMIT();                              // group g1 = tile 1 (possibly empty)

    {
        const int row  = tid >> 1;
        const int colh = (tid & 1) * 64;
        const float4* src = (const float4*)(Q + ((size_t)b * NQ + q0 + row) * DIM + colh);
        const float scale = 0.08838834764831845f;  // 1/sqrt(128)
        #pragma unroll
        for (int i = 0; i < 16; ++i) {
            float4 v = src[i];
            int byte = row * KROW + (colh + i * 4) * 2;
            *(uint32_t*)(smem + SQ + byte)     = pack2(v.x * scale, v.y * scale);
            *(uint32_t*)(smem + SQ + byte + 4) = pack2(v.z * scale, v.w * scale);
        }
    }
    __syncthreads();   // Q visible for fragment build

    // ---- Loop-invariant Q A-fragments (8 k-steps) ----
    uint32_t qh[8][4];
    {
        const int r  = warp * 16 + (lane >> 2);
        const int cb = 4 * (lane & 3);
        #pragma unroll
        for (int ks = 0; ks < 8; ++ks) {
            int o0 = r * KROW + ks * 32 + cb;
            int o1 = o0 + 8 * KROW;
            qh[ks][0] = *(uint32_t*)(smem + SQ + o0);
            qh[ks][1] = *(uint32_t*)(smem + SQ + o1);
            qh[ks][2] = *(uint32_t*)(smem + SQ + o0 + 16);
            qh[ks][3] = *(uint32_t*)(smem + SQ + o1 + 16);
        }
    }

    float o[16][4];
    #pragma unroll
    for (int j = 0; j < 16; ++j)
        #pragma unroll
        for (int c = 0; c < 4; ++c) o[j][c] = 0.0f;
    float lsum0 = 0.0f, lsum1 = 0.0f;

    // ---- 3-stage pipelined KV loop: ONE barrier per tile ----
    // At iter it: wait (tile it resident, tile it+1 may fly), sync (also fences
    // last readers of stage (it+2)%3 = compute of tile it-1), issue tile it+2.
    for (int it = 0; it < nt; ++it) {
        CPA_WAIT1();
        __syncthreads();
        if (it + 2 < nt)
            issue_tile(base, (it + 2) % NSTAGE, tid, (it + 2) * BN, gk, gv);
        CPA_COMMIT();

        const uint32_t sb = base + (it % NSTAGE) * STAGE;
        const int n0 = it * BN;
        const int limit = vlen - n0;

        // ---- GEMM1 (1-term fp16: Q @ K^T) + softmax + fp16 P pack ----
        uint32_t pah[4][4];
        #pragma unroll
        for (int j = 0; j < 8; ++j) {
            float sa[4] = {0.f, 0.f, 0.f, 0.f};
            #pragma unroll
            for (int kp = 0; kp < 4; ++kp) {
                uint32_t addr = sb + SK + (j * 8 + (lane & 7)) * KROW
                              + (kp * 32 + (lane >> 3) * 8) * 2;
                uint32_t bh[4];
                ldsm4(bh, addr);
                mma16816(sa, qh[kp * 2],     bh[0], bh[1]);
                mma16816(sa, qh[kp * 2 + 1], bh[2], bh[3]);
            }
            const int colb = j * 8 + 2 * (lane & 3);
            float p0 = (colb     < limit) ? __expf(sa[0]) : 0.0f;
            float p1 = (colb + 1 < limit) ? __expf(sa[1]) : 0.0f;
            float p2 = (colb     < limit) ? __expf(sa[2]) : 0.0f;
            float p3 = (colb + 1 < limit) ? __expf(sa[3]) : 0.0f;
            lsum0 += p0 + p1;
            lsum1 += p2 + p3;
            const int kk = j >> 1, ro = (j & 1) * 2;
            pah[kk][ro]     = pack2(p0, p1);
            pah[kk][ro + 1] = pack2(p2, p3);
        }

        // ---- GEMM2 (1-term fp16: P @ V) via ldmatrix.trans on [key][dv] tile ----
        #pragma unroll
        for (int j2 = 0; j2 < 16; ++j2) {
            #pragma unroll
            for (int kp = 0; kp < 2; ++kp) {
                uint32_t addr = sb + SV
                              + (kp * 32 + (lane >> 3) * 8 + (lane & 7)) * KROW
                              + j2 * 16;
                uint32_t vh[4];
                ldsm4t(vh, addr);
                mma16816(o[j2], pah[kp * 2],     vh[0], vh[1]);
                mma16816(o[j2], pah[kp * 2 + 1], vh[2], vh[3]);
            }
        }
    }

    // ---- Epilogue ----
    lsum0 += __shfl_xor_sync(0xffffffffu, lsum0, 1);
    lsum0 += __shfl_xor_sync(0xffffffffu, lsum0, 2);
    lsum1 += __shfl_xor_sync(0xffffffffu, lsum1, 1);
    lsum1 += __shfl_xor_sync(0xffffffffu, lsum1, 2);
    const float inv0 = 1.0f / lsum0;
    const float inv1 = 1.0f / lsum1;

    const int rowA = q0 + warp * 16 + (lane >> 2);
    float* OA = O + ((size_t)b * NQ + rowA) * DVAL + 2 * (lane & 3);
    float* OB = OA + 8 * DVAL;
    #pragma unroll
    for (int j2 = 0; j2 < 16; ++j2) {
        float2 a = make_float2(o[j2][0] * inv0, o[j2][1] * inv0);
        float2 c = make_float2(o[j2][2] * inv1, o[j2][3] * inv1);
        *(float2*)(OA + j2 * 8) = a;
        *(float2*)(OB + j2 * 8) = c;
    }
}

extern "C" void kernel_launch(void* const* d_in, const int* in_sizes, int n_in,
                              void* d_out, int out_size)
{
    (void)in_sizes; (void)n_in; (void)out_size;
    const float* Q  = (const float*)d_in[0];
    const float* K  = (const float*)d_in[1];
    const float* V  = (const float*)d_in[2];
    const int*   VL = (const int*)  d_in[3];
    float* O = (float*)d_out;

    static int configured = 0;
    if (!configured) {
        cudaFuncSetAttribute(fa_mma_kernel,
                             cudaFuncAttributeMaxDynamicSharedMemorySize, SM_TOTAL);
        configured = 1;
    }

    kvconv_kernel<<<BATCH * NK * DIM / 4 / 256, 256>>>(K, V);

    dim3 grid(NQ / BM, BATCH);   // q-tile-fast (champion config)
    fa_mma_kernel<<<grid, NTHREADS, SM_TOTAL>>>(Q, VL, O);
}

// round 15
// speedup vs baseline: 1.1073x; 1.1073x over previous
#include <cuda_runtime.h>
#include <cuda_fp16.h>
#include <cstdint>

// ---------------- Problem constants ----------------
#define BATCH 16
#define NQ    2048
#define NK    2048
#define DIM   128
#define DVAL  128

// ---------------- Tiling ----------------
#define BM 64
#define BN 64
#define NTHREADS 128   // 4 warps; warp w owns q-rows [w*16, w*16+16)

// ---------------- Precomputed fp16 K + V (both natural [b][key][d] layout) ----------------
__device__ __half gK[BATCH * NK * DIM];
__device__ __half gV[BATCH * NK * DVAL];

// ---------------- SMEM layout (bytes) ----------------
// Per stage (both tiles 64 keys x 128 d fp16, padded row = 272 B, conflict-free):
#define KROW 272
#define SK    0
#define SV    17408                  // 64*272
#define STAGE 34816                  // 2*17408
// Q staging overlays stage-1 region (prologue only)
#define SQ    STAGE
#define SM_TOTAL (2 * STAGE)         // 69632 -> 2 CTAs/SM (champion regime)

// ---------------- PTX helpers ----------------
__device__ __forceinline__ uint32_t smem_u32(const void* p) {
    uint32_t a;
    asm("{ .reg .u64 t; cvta.to.shared.u64 t, %1; cvt.u32.u64 %0, t; }" : "=r"(a) : "l"(p));
    return a;
}
__device__ __forceinline__ void ldsm4(uint32_t* r, uint32_t addr) {
    asm volatile("ldmatrix.sync.aligned.m8n8.x4.shared.b16 {%0,%1,%2,%3}, [%4];"
                 : "=r"(r[0]), "=r"(r[1]), "=r"(r[2]), "=r"(r[3]) : "r"(addr));
}
__device__ __forceinline__ void ldsm4t(uint32_t* r, uint32_t addr) {
    asm volatile("ldmatrix.sync.aligned.m8n8.x4.trans.shared.b16 {%0,%1,%2,%3}, [%4];"
                 : "=r"(r[0]), "=r"(r[1]), "=r"(r[2]), "=r"(r[3]) : "r"(addr));
}
__device__ __forceinline__ void mma16816(float* c, const uint32_t* a, uint32_t b0, uint32_t b1) {
    asm volatile("mma.sync.aligned.m16n8k16.row.col.f32.f16.f16.f32 "
                 "{%0,%1,%2,%3}, {%4,%5,%6,%7}, {%8,%9}, {%0,%1,%2,%3};"
                 : "+f"(c[0]), "+f"(c[1]), "+f"(c[2]), "+f"(c[3])
                 : "r"(a[0]), "r"(a[1]), "r"(a[2]), "r"(a[3]), "r"(b0), "r"(b1));
}
#define CPA16(dst, src) \
    asm volatile("cp.async.cg.shared.global [%0], [%1], 16;" :: "r"(dst), "l"(src))
#define CPA_COMMIT() asm volatile("cp.async.commit_group;" ::: "memory")
#define CPA_WAIT1()  asm volatile("cp.async.wait_group 1;" ::: "memory")

// fp32 pair -> packed fp16x2
__device__ __forceinline__ uint32_t pack2(float a, float b) {
    __half2 H = __floats2half2_rn(a, b);
    return *reinterpret_cast<uint32_t*>(&H);
}

// ---------------- Fused precompute: K and V -> fp16, same layout ----------------
__global__ void kvconv_kernel(const float* __restrict__ K, const float* __restrict__ V) {
    const int i = blockIdx.x * blockDim.x + threadIdx.x;   // over float4s
    float4 k = ((const float4*)K)[i];
    float4 v = ((const float4*)V)[i];
    ((uint2*)gK)[i] = make_uint2(pack2(k.x, k.y), pack2(k.z, k.w));
    ((uint2*)gV)[i] = make_uint2(pack2(v.x, v.y), pack2(v.z, v.w));
}

// ---------------- Tile prefetch (all 128 threads; 16 CPA16 each) ----------------
__device__ __forceinline__ void issue_tile(uint32_t base, int st, int tid, int n0,
                                           const __half* __restrict__ gk,
                                           const __half* __restrict__ gv) {
    const uint32_t sb = base + st * STAGE;
    #pragma unroll
    for (int i = 0; i < 8; ++i) {              // K: 64 keys x 256 B
        int c = tid + NTHREADS * i;
        int key = c >> 4, seg = c & 15;
        CPA16(sb + SK + key * KROW + seg * 16,
              gk + (size_t)(n0 + key) * DIM + seg * 8);
    }
    #pragma unroll
    for (int i = 0; i < 8; ++i) {              // V: 64 keys x 256 B (same pattern)
        int c = tid + NTHREADS * i;
        int key = c >> 4, seg = c & 15;
        CPA16(sb + SV + key * KROW + seg * 16,
              gv + (size_t)(n0 + key) * DVAL + seg * 8);
    }
}

// ---------------- Per-tile compute (GEMM1 + softmax + GEMM2) ----------------
// MASKED=false: common full-tile path, zero masking ALU.
template <bool MASKED>
__device__ __forceinline__ void compute_tile(
    uint32_t sb, int lane, int limit,
    const uint32_t qh[8][4], float o[16][4], float& lsum0, float& lsum1)
{
    // Hoisted lane-invariant address bases
    const uint32_t kbase = sb + SK + (lane & 7) * KROW + ((lane >> 3) * 8) * 2;
    const uint32_t vbase = sb + SV + ((lane >> 3) * 8 + (lane & 7)) * KROW;

    // ---- GEMM1 (1-term fp16: Q @ K^T) + softmax + fp16 P pack ----
    uint32_t pah[4][4];
    #pragma unroll
    for (int j = 0; j < 8; ++j) {
        float sa[4] = {0.f, 0.f, 0.f, 0.f};
        #pragma unroll
        for (int kp = 0; kp < 4; ++kp) {
            uint32_t bh[4];
            ldsm4(bh, kbase + j * (8 * KROW) + kp * 64);
            mma16816(sa, qh[kp * 2],     bh[0], bh[1]);
            mma16816(sa, qh[kp * 2 + 1], bh[2], bh[3]);
        }
        float p0, p1, p2, p3;
        if (MASKED) {
            const int colb = j * 8 + 2 * (lane & 3);
            p0 = (colb     < limit) ? __expf(sa[0]) : 0.0f;
            p1 = (colb + 1 < limit) ? __expf(sa[1]) : 0.0f;
            p2 = (colb     < limit) ? __expf(sa[2]) : 0.0f;
            p3 = (colb + 1 < limit) ? __expf(sa[3]) : 0.0f;
        } else {
            p0 = __expf(sa[0]);
            p1 = __expf(sa[1]);
            p2 = __expf(sa[2]);
            p3 = __expf(sa[3]);
        }
        lsum0 += p0 + p1;
        lsum1 += p2 + p3;
        const int kk = j >> 1, ro = (j & 1) * 2;
        pah[kk][ro]     = pack2(p0, p1);
        pah[kk][ro + 1] = pack2(p2, p3);
    }

    // ---- GEMM2 (1-term fp16: P @ V) via ldmatrix.trans on [key][dv] tile ----
    #pragma unroll
    for (int j2 = 0; j2 < 16; ++j2) {
        #pragma unroll
        for (int kp = 0; kp < 2; ++kp) {
            uint32_t vh[4];
            ldsm4t(vh, vbase + kp * (32 * KROW) + j2 * 16);
            mma16816(o[j2], pah[kp * 2],     vh[0], vh[1]);
            mma16816(o[j2], pah[kp * 2 + 1], vh[2], vh[3]);
        }
    }
}

// ---------------- Main attention kernel ----------------
__global__ __launch_bounds__(NTHREADS, 2)    // occ 2: champion regime (regs ~242)
void fa_mma_kernel(const float* __restrict__ Q, const int* __restrict__ VL,
                   float* __restrict__ O)
{
    extern __shared__ char smem[];
    const uint32_t base = smem_u32(smem);
    const int tid  = threadIdx.x;
    const int warp = tid >> 5;
    const int lane = tid & 31;
    const int b    = blockIdx.y;        // q-tile-fast grid (champion config)
    const int q0   = blockIdx.x * BM;
    const int vlen = VL[b];
    const int nt   = (vlen + BN - 1) / BN;

    const __half* gk = gK + (size_t)b * NK * DIM;
    const __half* gv = gV + (size_t)b * NK * DVAL;

    // ---- Prologue: tile 0 -> stage 0 (async) while Q (fp16) stages into stage-1 area ----
    issue_tile(base, 0, tid, 0, gk, gv);
    CPA_COMMIT();

    {
        const int row  = tid >> 1;
        const int colh = (tid & 1) * 64;
        const float4* src = (const float4*)(Q + ((size_t)b * NQ + q0 + row) * DIM + colh);
        const float scale = 0.08838834764831845f;  // 1/sqrt(128)
        #pragma unroll
        for (int i = 0; i < 16; ++i) {
            float4 v = src[i];
            int byte = row * KROW + (colh + i * 4) * 2;
            *(uint32_t*)(smem + SQ + byte)     = pack2(v.x * scale, v.y * scale);
            *(uint32_t*)(smem + SQ + byte + 4) = pack2(v.z * scale, v.w * scale);
        }
    }
    __syncthreads();

    // ---- Loop-invariant Q A-fragments (8 k-steps) ----
    uint32_t qh[8][4];
    {
        const int r  = warp * 16 + (lane >> 2);
        const int cb = 4 * (lane & 3);
        #pragma unroll
        for (int ks = 0; ks < 8; ++ks) {
            int o0 = r * KROW + ks * 32 + cb;
            int o1 = o0 + 8 * KROW;
            qh[ks][0] = *(uint32_t*)(smem + SQ + o0);
            qh[ks][1] = *(uint32_t*)(smem + SQ + o1);
            qh[ks][2] = *(uint32_t*)(smem + SQ + o0 + 16);
            qh[ks][3] = *(uint32_t*)(smem + SQ + o1 + 16);
        }
    }

    float o[16][4];
    #pragma unroll
    for (int j = 0; j < 16; ++j)
        #pragma unroll
        for (int c = 0; c < 4; ++c) o[j][c] = 0.0f;
    float lsum0 = 0.0f, lsum1 = 0.0f;

    // ---- Pipelined KV loop (2-stage, champion structure) ----
    for (int it = 0; it < nt; ++it) {
        __syncthreads();   // all warps done with buf[(it+1)&1] (and Q frags at it=0)
        if (it + 1 < nt)
            issue_tile(base, (it + 1) & 1, tid, (it + 1) * BN, gk, gv);
        CPA_COMMIT();
        CPA_WAIT1();       // tile it resident
        __syncthreads();

        const uint32_t sb = base + (it & 1) * STAGE;
        const int limit = vlen - it * BN;

        if (limit >= BN)
            compute_tile<false>(sb, lane, limit, qh, o, lsum0, lsum1);
        else
            compute_tile<true>(sb, lane, limit, qh, o, lsum0, lsum1);
    }

    // ---- Epilogue ----
    lsum0 += __shfl_xor_sync(0xffffffffu, lsum0, 1);
    lsum0 += __shfl_xor_sync(0xffffffffu, lsum0, 2);
    lsum1 += __shfl_xor_sync(0xffffffffu, lsum1, 1);
    lsum1 += __shfl_xor_sync(0xffffffffu, lsum1, 2);
    const float inv0 = 1.0f / lsum0;
    const float inv1 = 1.0f / lsum1;

    const int rowA = q0 + warp * 16 + (lane >> 2);
    float* OA = O + ((size_t)b * NQ + rowA) * DVAL + 2 * (lane & 3);
    float* OB = OA + 8 * DVAL;
    #pragma unroll
    for (int j2 = 0; j2 < 16; ++j2) {
        float2 a = make_float2(o[j2][0] * inv0, o[j2][1] * inv0);
        float2 c = make_float2(o[j2][2] * inv1, o[j2][3] * inv1);
        *(float2*)(OA + j2 * 8) = a;
        *(float2*)(OB + j2 * 8) = c;
    }
}

extern "C" void kernel_launch(void* const* d_in, const int* in_sizes, int n_in,
                              void* d_out, int out_size)
{
    (void)in_sizes; (void)n_in; (void)out_size;
    const float* Q  = (const float*)d_in[0];
    const float* K  = (const float*)d_in[1];
    const float* V  = (const float*)d_in[2];
    const int*   VL = (const int*)  d_in[3];
    float* O = (float*)d_out;

    static int configured = 0;
    if (!configured) {
        cudaFuncSetAttribute(fa_mma_kernel,
                             cudaFuncAttributeMaxDynamicSharedMemorySize, SM_TOTAL);
        configured = 1;
    }

    kvconv_kernel<<<BATCH * NK * DIM / 4 / 256, 256>>>(K, V);

    dim3 grid(NQ / BM, BATCH);   // q-tile-fast (champion config)
    fa_mma_kernel<<<grid, NTHREADS, SM_TOTAL>>>(Q, VL, O);
}

// round 16
// speedup vs baseline: 1.3335x; 1.2042x over previous
#include <cuda_runtime.h>
#include <cuda_fp16.h>
#include <cstdint>

// ---------------- Problem constants ----------------
#define BATCH 16
#define NQ    2048
#define NK    2048
#define DIM   128
#define DVAL  128

// ---------------- Tiling ----------------
#define BM 64
#define BN 64
#define NTHREADS 128   // 4 warps; warp w owns q-rows [w*16, w*16+16)

// ---------------- Precomputed fp16 K + V (both natural [b][key][d] layout) ----------------
__device__ __half gK[BATCH * NK * DIM];
__device__ __half gV[BATCH * NK * DVAL];
__device__ int    gOrder[BATCH];     // batches sorted by vlen descending (LPT dispatch)

// ---------------- SMEM layout (bytes) ----------------
// Per stage (both tiles 64 keys x 128 d fp16, padded row = 272 B, conflict-free):
#define KROW 272
#define SK    0
#define SV    17408                  // 64*272
#define STAGE 34816                  // 2*17408
// Q staging overlays stage-1 region (prologue only)
#define SQ    STAGE
#define SM_TOTAL (2 * STAGE)         // 69632 -> 2 CTAs/SM (champion regime)

// ---------------- PTX helpers ----------------
__device__ __forceinline__ uint32_t smem_u32(const void* p) {
    uint32_t a;
    asm("{ .reg .u64 t; cvta.to.shared.u64 t, %1; cvt.u32.u64 %0, t; }" : "=r"(a) : "l"(p));
    return a;
}
__device__ __forceinline__ void ldsm4(uint32_t* r, uint32_t addr) {
    asm volatile("ldmatrix.sync.aligned.m8n8.x4.shared.b16 {%0,%1,%2,%3}, [%4];"
                 : "=r"(r[0]), "=r"(r[1]), "=r"(r[2]), "=r"(r[3]) : "r"(addr));
}
__device__ __forceinline__ void ldsm4t(uint32_t* r, uint32_t addr) {
    asm volatile("ldmatrix.sync.aligned.m8n8.x4.trans.shared.b16 {%0,%1,%2,%3}, [%4];"
                 : "=r"(r[0]), "=r"(r[1]), "=r"(r[2]), "=r"(r[3]) : "r"(addr));
}
__device__ __forceinline__ void mma16816(float* c, const uint32_t* a, uint32_t b0, uint32_t b1) {
    asm volatile("mma.sync.aligned.m16n8k16.row.col.f32.f16.f16.f32 "
                 "{%0,%1,%2,%3}, {%4,%5,%6,%7}, {%8,%9}, {%0,%1,%2,%3};"
                 : "+f"(c[0]), "+f"(c[1]), "+f"(c[2]), "+f"(c[3])
                 : "r"(a[0]), "r"(a[1]), "r"(a[2]), "r"(a[3]), "r"(b0), "r"(b1));
}
#define CPA16(dst, src) \
    asm volatile("cp.async.cg.shared.global [%0], [%1], 16;" :: "r"(dst), "l"(src))
#define CPA_COMMIT() asm volatile("cp.async.commit_group;" ::: "memory")
#define CPA_WAIT1()  asm volatile("cp.async.wait_group 1;" ::: "memory")

// fp32 pair -> packed fp16x2
__device__ __forceinline__ uint32_t pack2(float a, float b) {
    __half2 H = __floats2half2_rn(a, b);
    return *reinterpret_cast<uint32_t*>(&H);
}

// ---------------- Fused precompute: K and V -> fp16, same layout ----------------
__global__ void kvconv_kernel(const float* __restrict__ K, const float* __restrict__ V) {
    const int i = blockIdx.x * blockDim.x + threadIdx.x;   // over float4s
    float4 k = ((const float4*)K)[i];
    float4 v = ((const float4*)V)[i];
    ((uint2*)gK)[i] = make_uint2(pack2(k.x, k.y), pack2(k.z, k.w));
    ((uint2*)gV)[i] = make_uint2(pack2(v.x, v.y), pack2(v.z, v.w));
}

// ---------------- LPT order: argsort valid_lens descending (16 elems, 1 thread) ----------------
__global__ void order_kernel(const int* __restrict__ VL) {
    if (threadIdx.x == 0 && blockIdx.x == 0) {
        int idx[BATCH], len[BATCH];
        #pragma unroll
        for (int i = 0; i < BATCH; ++i) { idx[i] = i; len[i] = VL[i]; }
        // selection sort, stable by index (deterministic)
        #pragma unroll
        for (int i = 0; i < BATCH - 1; ++i) {
            int best = i;
            #pragma unroll
            for (int j = i + 1; j < BATCH; ++j)
                if (len[j] > len[best]) best = j;
            int tl = len[i]; len[i] = len[best]; len[best] = tl;
            int ti = idx[i]; idx[i] = idx[best]; idx[best] = ti;
        }
        #pragma unroll
        for (int i = 0; i < BATCH; ++i) gOrder[i] = idx[i];
    }
}

// ---------------- Tile prefetch (all 128 threads; 16 CPA16 each) ----------------
__device__ __forceinline__ void issue_tile(uint32_t base, int st, int tid, int n0,
                                           const __half* __restrict__ gk,
                                           const __half* __restrict__ gv) {
    const uint32_t sb = base + st * STAGE;
    #pragma unroll
    for (int i = 0; i < 8; ++i) {              // K: 64 keys x 256 B
        int c = tid + NTHREADS * i;
        int key = c >> 4, seg = c & 15;
        CPA16(sb + SK + key * KROW + seg * 16,
              gk + (size_t)(n0 + key) * DIM + seg * 8);
    }
    #pragma unroll
    for (int i = 0; i < 8; ++i) {              // V: 64 keys x 256 B (same pattern)
        int c = tid + NTHREADS * i;
        int key = c >> 4, seg = c & 15;
        CPA16(sb + SV + key * KROW + seg * 16,
              gv + (size_t)(n0 + key) * DVAL + seg * 8);
    }
}

// ---------------- Per-tile compute (GEMM1 + softmax + GEMM2) ----------------
template <bool MASKED>
__device__ __forceinline__ void compute_tile(
    uint32_t sb, int lane, int limit,
    const uint32_t qh[8][4], float o[16][4], float& lsum0, float& lsum1)
{
    const uint32_t kbase = sb + SK + (lane & 7) * KROW + ((lane >> 3) * 8) * 2;
    const uint32_t vbase = sb + SV + ((lane >> 3) * 8 + (lane & 7)) * KROW;

    // ---- GEMM1 (1-term fp16: Q @ K^T) + softmax + fp16 P pack ----
    uint32_t pah[4][4];
    #pragma unroll
    for (int j = 0; j < 8; ++j) {
        float sa[4] = {0.f, 0.f, 0.f, 0.f};
        #pragma unroll
        for (int kp = 0; kp < 4; ++kp) {
            uint32_t bh[4];
            ldsm4(bh, kbase + j * (8 * KROW) + kp * 64);
            mma16816(sa, qh[kp * 2],     bh[0], bh[1]);
            mma16816(sa, qh[kp * 2 + 1], bh[2], bh[3]);
        }
        float p0, p1, p2, p3;
        if (MASKED) {
            const int colb = j * 8 + 2 * (lane & 3);
            p0 = (colb     < limit) ? __expf(sa[0]) : 0.0f;
            p1 = (colb + 1 < limit) ? __expf(sa[1]) : 0.0f;
            p2 = (colb     < limit) ? __expf(sa[2]) : 0.0f;
            p3 = (colb + 1 < limit) ? __expf(sa[3]) : 0.0f;
        } else {
            p0 = __expf(sa[0]);
            p1 = __expf(sa[1]);
            p2 = __expf(sa[2]);
            p3 = __expf(sa[3]);
        }
        lsum0 += p0 + p1;
        lsum1 += p2 + p3;
        const int kk = j >> 1, ro = (j & 1) * 2;
        pah[kk][ro]     = pack2(p0, p1);
        pah[kk][ro + 1] = pack2(p2, p3);
    }

    // ---- GEMM2 (1-term fp16: P @ V) via ldmatrix.trans on [key][dv] tile ----
    #pragma unroll
    for (int j2 = 0; j2 < 16; ++j2) {
        #pragma unroll
        for (int kp = 0; kp < 2; ++kp) {
            uint32_t vh[4];
            ldsm4t(vh, vbase + kp * (32 * KROW) + j2 * 16);
            mma16816(o[j2], pah[kp * 2],     vh[0], vh[1]);
            mma16816(o[j2], pah[kp * 2 + 1], vh[2], vh[3]);
        }
    }
}

// ---------------- Main attention kernel ----------------
__global__ __launch_bounds__(NTHREADS, 2)    // occ 2: champion regime (regs ~241)
void fa_mma_kernel(const float* __restrict__ Q, const int* __restrict__ VL,
                   float* __restrict__ O)
{
    extern __shared__ char smem[];
    const uint32_t base = smem_u32(smem);
    const int tid  = threadIdx.x;
    const int warp = tid >> 5;
    const int lane = tid & 31;
    const int b    = gOrder[blockIdx.y];   // LPT: heaviest batches dispatch first
    const int q0   = blockIdx.x * BM;
    const int vlen = VL[b];
    const int nt   = (vlen + BN - 1) / BN;

    const __half* gk = gK + (size_t)b * NK * DIM;
    const __half* gv = gV + (size_t)b * NK * DVAL;

    // ---- Prologue: tile 0 -> stage 0 (async) while Q (fp16) stages into stage-1 area ----
    issue_tile(base, 0, tid, 0, gk, gv);
    CPA_COMMIT();

    {
        const int row  = tid >> 1;
        const int colh = (tid & 1) * 64;
        const float4* src = (const float4*)(Q + ((size_t)b * NQ + q0 + row) * DIM + colh);
        const float scale = 0.08838834764831845f;  // 1/sqrt(128)
        #pragma unroll
        for (int i = 0; i < 16; ++i) {
            float4 v = src[i];
            int byte = row * KROW + (colh + i * 4) * 2;
            *(uint32_t*)(smem + SQ + byte)     = pack2(v.x * scale, v.y * scale);
            *(uint32_t*)(smem + SQ + byte + 4) = pack2(v.z * scale, v.w * scale);
        }
    }
    __syncthreads();

    // ---- Loop-invariant Q A-fragments (8 k-steps) ----
    uint32_t qh[8][4];
    {
        const int r  = warp * 16 + (lane >> 2);
        const int cb = 4 * (lane & 3);
        #pragma unroll
        for (int ks = 0; ks < 8; ++ks) {
            int o0 = r * KROW + ks * 32 + cb;
            int o1 = o0 + 8 * KROW;
            qh[ks][0] = *(uint32_t*)(smem + SQ + o0);
            qh[ks][1] = *(uint32_t*)(smem + SQ + o1);
            qh[ks][2] = *(uint32_t*)(smem + SQ + o0 + 16);
            qh[ks][3] = *(uint32_t*)(smem + SQ + o1 + 16);
        }
    }

    float o[16][4];
    #pragma unroll
    for (int j = 0; j < 16; ++j)
        #pragma unroll
        for (int c = 0; c < 4; ++c) o[j][c] = 0.0f;
    float lsum0 = 0.0f, lsum1 = 0.0f;

    // ---- Pipelined KV loop (2-stage, champion structure) ----
    for (int it = 0; it < nt; ++it) {
        __syncthreads();   // all warps done with buf[(it+1)&1] (and Q frags at it=0)
        if (it + 1 < nt)
            issue_tile(base, (it + 1) & 1, tid, (it + 1) * BN, gk, gv);
        CPA_COMMIT();
        CPA_WAIT1();       // tile it resident
        __syncthreads();

        const uint32_t sb = base + (it & 1) * STAGE;
        const int limit = vlen - it * BN;

        if (limit >= BN)
            compute_tile<false>(sb, lane, limit, qh, o, lsum0, lsum1);
        else
            compute_tile<true>(sb, lane, limit, qh, o, lsum0, lsum1);
    }

    // ---- Epilogue ----
    lsum0 += __shfl_xor_sync(0xffffffffu, lsum0, 1);
    lsum0 += __shfl_xor_sync(0xffffffffu, lsum0, 2);
    lsum1 += __shfl_xor_sync(0xffffffffu, lsum1, 1);
    lsum1 += __shfl_xor_sync(0xffffffffu, lsum1, 2);
    const float inv0 = 1.0f / lsum0;
    const float inv1 = 1.0f / lsum1;

    const int rowA = q0 + warp * 16 + (lane >> 2);
    float* OA = O + ((size_t)b * NQ + rowA) * DVAL + 2 * (lane & 3);
    float* OB = OA + 8 * DVAL;
    #pragma unroll
    for (int j2 = 0; j2 < 16; ++j2) {
        float2 a = make_float2(o[j2][0] * inv0, o[j2][1] * inv0);
        float2 c = make_float2(o[j2][2] * inv1, o[j2][3] * inv1);
        *(float2*)(OA + j2 * 8) = a;
        *(float2*)(OB + j2 * 8) = c;
    }
}

extern "C" void kernel_launch(void* const* d_in, const int* in_sizes, int n_in,
                              void* d_out, int out_size)
{
    (void)in_sizes; (void)n_in; (void)out_size;
    const float* Q  = (const float*)d_in[0];
    const float* K  = (const float*)d_in[1];
    const float* V  = (const float*)d_in[2];
    const int*   VL = (const int*)  d_in[3];
    float* O = (float*)d_out;

    static int configured = 0;
    if (!configured) {
        cudaFuncSetAttribute(fa_mma_kernel,
                             cudaFuncAttributeMaxDynamicSharedMemorySize, SM_TOTAL);
        configured = 1;
    }

    order_kernel<<<1, 32>>>(VL);
    kvconv_kernel<<<BATCH * NK * DIM / 4 / 256, 256>>>(K, V);

    dim3 grid(NQ / BM, BATCH);   // q-tile-fast, batches remapped heavy-first via gOrder
    fa_mma_kernel<<<grid, NTHREADS, SM_TOTAL>>>(Q, VL, O);
}